// round 13
// baseline (speedup 1.0000x reference)
#include <cuda_runtime.h>
#include <cuda_fp16.h>
#include <cstdint>
#include <math.h>

#define NRE 8
#define NEXP 10
#define XS 132     // fp32 x staging row stride (floats)

// ---- dynamic smem byte offsets ----
#define XP_OFF   0          // 67584: fp32 x staging [128][132] (router + pack source)
#define XF_OFF   67584      // 32768: x A-frags fp16 [t8][k8][l32] uint4
#define HF_OFF   100352     // 32768: h A-frags fp16 [t8][k8][l32] uint4
#define WR_OFF   133120     // 65536: ring 2 x 32KB (buf0 = W1, buf1 = W2)
#define MGS_OFF  198656     // 4096
#define B1S_OFF  202752     // 5120
#define B2S_OFF  207872     // 5120
#define SMEM_BYTES 212992

// fp16 B-frag weight images: chunk c = 2e + {0:W1_e, 1:W2_e}, 32KB each.
// in-chunk: uint2 entry [(k8)*16 + j][l32] = { h2(W[16k+2c][n], W[16k+2c+1][n]),
//                                              h2(W[16k+2c+8][n], W[16k+2c+9][n]) }, n = 8j+g
__device__ __align__(16) uint2 g_wfrag[20 * 4096];

// ---------------- helpers ----------------
static __device__ __forceinline__ uint32_t s2u(const void* p) {
    uint32_t a;
    asm("{ .reg .u64 t; cvta.to.shared.u64 t, %1; cvt.u32.u64 %0, t; }" : "=r"(a) : "l"(p));
    return a;
}
static __device__ __forceinline__ unsigned h2u(__half2 h) {
    return *reinterpret_cast<unsigned*>(&h);
}
static __device__ __forceinline__ void mma_f16(float d[4], const unsigned a[4], const unsigned b[2]) {
    asm volatile(
        "mma.sync.aligned.m16n8k16.row.col.f32.f16.f16.f32 "
        "{%0,%1,%2,%3}, {%4,%5,%6,%7}, {%8,%9}, {%0,%1,%2,%3};"
        : "+f"(d[0]), "+f"(d[1]), "+f"(d[2]), "+f"(d[3])
        : "r"(a[0]), "r"(a[1]), "r"(a[2]), "r"(a[3]), "r"(b[0]), "r"(b[1]));
}
static __device__ __forceinline__ float gelu_f(float x) {
    float u = 0.7978845608028654f * (x + 0.044715f * x * x * x);
    float ex = __expf(2.0f * u);
    float t = 1.0f - 2.0f / (ex + 1.0f);       // tanh(u), inf-safe
    return 0.5f * x * (1.0f + t);
}
static __device__ __forceinline__ void cp16(uint32_t dst, const void* src) {
    asm volatile("cp.async.cg.shared.global [%0], [%1], 16;" :: "r"(dst), "l"(src) : "memory");
}
#define CP_COMMIT() asm volatile("cp.async.commit_group;" ::: "memory")
#define CP_WAIT1()  asm volatile("cp.async.wait_group 1;" ::: "memory")

// ============ prep: weights -> fp16 B-frag chunks (one matrix per block) ============
__global__ void __launch_bounds__(256, 1)
prep_kernel(const float* __restrict__ We1, const float* __restrict__ Ws1,
            const float* __restrict__ We2, const float* __restrict__ Ws2) {
    extern __shared__ float ws[];          // [128][132]
    int m = blockIdx.x;                    // 0..7 We1, 8..9 Ws1, 10..17 We2, 18..19 Ws2
    const float* W;
    int ee, isw2;
    if (m < 8)       { W = We1 + m * 16384;        ee = m;      isw2 = 0; }
    else if (m < 10) { W = Ws1 + (m - 8) * 16384;  ee = m;      isw2 = 0; }
    else if (m < 18) { W = We2 + (m - 10) * 16384; ee = m - 10; isw2 = 1; }
    else             { W = Ws2 + (m - 18) * 16384; ee = m - 10; isw2 = 1; }
    const int tid = threadIdx.x;
#pragma unroll
    for (int it = 0; it < 16; it++) {
        int idx = it * 256 + tid;
        int row = idx >> 5, c4 = (idx & 31) << 2;
        *reinterpret_cast<float4*>(ws + row * XS + c4) =
            *reinterpret_cast<const float4*>(W + row * 128 + c4);
    }
    __syncthreads();
    uint2* dst = g_wfrag + (size_t)(2 * ee + isw2) * 4096;
#pragma unroll
    for (int it = 0; it < 16; it++) {
        int i = it * 256 + tid;            // 0..4095: [k8][j16][l32]
        int l = i & 31, j = (i >> 5) & 15, k = i >> 9;
        int g = l >> 2, c = l & 3;
        int n = 8 * j + g;
        int r = 16 * k + 2 * c;
        __half2 lo = __floats2half2_rn(ws[r * XS + n],       ws[(r + 1) * XS + n]);
        __half2 hi = __floats2half2_rn(ws[(r + 8) * XS + n], ws[(r + 9) * XS + n]);
        uint2 o;
        o.x = h2u(lo);
        o.y = h2u(hi);
        dst[i] = o;
    }
}

// ============ main fused kernel ============
__global__ void __launch_bounds__(256, 1)
moe_kernel(const float* __restrict__ x,
           const float* __restrict__ Wr1, const float* __restrict__ br1,
           const float* __restrict__ Wr2, const float* __restrict__ br2,
           const float* __restrict__ be1, const float* __restrict__ be2,
           const float* __restrict__ bs1, const float* __restrict__ bs2,
           float* __restrict__ out) {
    extern __shared__ char smem[];
    const uint32_t sb = s2u(smem);
    float* xp  = (float*)(smem + XP_OFF);
    uint4* xfu = (uint4*)(smem + XF_OFF);
    uint4* hfu = (uint4*)(smem + HF_OFF);
    float* mgs = (float*)(smem + MGS_OFF);
    float* b1s = (float*)(smem + B1S_OFF);
    float* b2s = (float*)(smem + B2S_OFF);
    // router scratch overlays XF (packed only after router completes)
    float* rW1 = (float*)(smem + XF_OFF);
    float* rb1 = rW1 + 2048;
    float* rW2 = rW1 + 2064;
    float* rb2 = rW1 + 2192;
    float* rfb = rW1 + 2208;

    const int tid  = threadIdx.x;
    const int lane = tid & 31;
    const int wid  = tid >> 5;
    const int g    = lane >> 2;
    const int c    = lane & 3;
    const int t0   = (wid >> 1) * 2;       // first 16-row tile of this warp
    const int mrow = t0 * 16;
    const int jb   = (wid & 1) * 8;        // first n8 tile
    const int ncol = jb * 8;
    const int kb2  = (wid & 1) * 4;        // warp's k'-slice base for h A-frags
    const long base = (long)blockIdx.x * 128;

    // ---- issue first two 32KB chunks (W1_0 -> buf0, W2_0 -> buf1) ----
    {
        const char* src0 = (const char*)g_wfrag;
        uint32_t d0 = sb + WR_OFF, d1 = sb + WR_OFF + 32768u;
#pragma unroll
        for (int i = 0; i < 8; i++) { uint32_t o = (uint32_t)(tid + i * 256) * 16u; cp16(d0 + o, src0 + o); }
        CP_COMMIT();
#pragma unroll
        for (int i = 0; i < 8; i++) { uint32_t o = (uint32_t)(tid + i * 256) * 16u; cp16(d1 + o, src0 + 32768 + o); }
        CP_COMMIT();
    }

    // ---- stage x (fp32) + biases + router weights ----
#pragma unroll
    for (int it = 0; it < 16; it++) {
        int idx = it * 256 + tid;
        int row = idx >> 5, c4 = (idx & 31) << 2;
        float4 v = *reinterpret_cast<const float4*>(x + (base + row) * 128 + c4);
        *reinterpret_cast<float4*>(xp + row * XS + c4) = v;
    }
    for (int i = tid; i < 1280; i += 256) b1s[i] = (i < 1024) ? be1[i] : bs1[i - 1024];
    for (int i = tid; i < 1280; i += 256) b2s[i] = (i < 1024) ? be2[i] : bs2[i - 1024];
    for (int i = tid; i < 2048; i += 256) rW1[i] = Wr1[i];
    if (tid < 16)  rb1[tid] = br1[tid];
    if (tid < 128) rW2[tid] = Wr2[tid];
    if (tid < 8)   rb2[tid] = br2[tid];
    __syncthreads();

    // ---- router stage 1 (fp32, full precision) ----
    {
        int tok = tid & 127, jfb = (tid >> 7) * 8;
        float rf[8];
#pragma unroll
        for (int j = 0; j < 8; j++) rf[j] = rb1[jfb + j];
        for (int h = 0; h < 128; h++) {
            float xv = xp[tok * XS + h];
#pragma unroll
            for (int j = 0; j < 8; j++) rf[j] += xv * rW1[h * 16 + jfb + j];
        }
#pragma unroll
        for (int j = 0; j < 8; j++) rfb[tok * 16 + jfb + j] = fmaxf(rf[j], 0.0f);
    }
    __syncthreads();
    // ---- router stage 2: softmax -> threshold -> renorm ----
    if (tid < 128) {
        float lg[8];
#pragma unroll
        for (int e = 0; e < 8; e++) lg[e] = rb2[e];
#pragma unroll
        for (int r = 0; r < 16; r++) {
            float v = rfb[tid * 16 + r];
#pragma unroll
            for (int e = 0; e < 8; e++) lg[e] += v * rW2[r * 8 + e];
        }
        float mx = lg[0];
#pragma unroll
        for (int e = 1; e < 8; e++) mx = fmaxf(mx, lg[e]);
        float s = 0.0f, gt[8];
#pragma unroll
        for (int e = 0; e < 8; e++) { gt[e] = expf(lg[e] - mx); s += gt[e]; }
        float inv = 1.0f / s, msum = 0.0f;
#pragma unroll
        for (int e = 0; e < 8; e++) {
            float gv = gt[e] * inv;
            gv = (gv > 0.125f) ? gv : 0.0f;
            gt[e] = gv; msum += gv;
        }
        float innorm = 1.0f / (msum + 1e-8f);
#pragma unroll
        for (int e = 0; e < 8; e++) mgs[tid * 8 + e] = gt[e] * innorm;
    }
    __syncthreads();            // router scratch in XF now dead

    // ---- pack x -> XF fp16 A-frags [t8][k8][l32] uint4 ----
#pragma unroll
    for (int it = 0; it < 8; it++) {
        int i = it * 256 + tid;            // = (t*8+k)*32 + l
        int l = i & 31, k = (i >> 5) & 7, t = i >> 8;
        int gg = l >> 2, cc = l & 3;
        const float* p0 = xp + (16 * t + gg) * XS + 16 * k + 2 * cc;
        uint4 v;
        v.x = h2u(__floats2half2_rn(p0[0], p0[1]));                       // row g,   k 2c..2c+1
        v.y = h2u(__floats2half2_rn(p0[8 * XS], p0[8 * XS + 1]));         // row g+8
        v.z = h2u(__floats2half2_rn(p0[8], p0[9]));                       // row g,   k 2c+8..2c+9
        v.w = h2u(__floats2half2_rn(p0[8 * XS + 8], p0[8 * XS + 9]));     // row g+8
        xfu[i] = v;
    }
    __syncthreads();

    float facc[2][8][4];
#pragma unroll
    for (int i = 0; i < 2; i++)
#pragma unroll
        for (int j = 0; j < 8; j++)
#pragma unroll
            for (int r = 0; r < 4; r++) facc[i][j][r] = 0.0f;

    const uint2* wr0 = (const uint2*)(smem + WR_OFF);           // W1 chunk
    const uint2* wr1 = (const uint2*)(smem + WR_OFF + 32768);   // W2 chunk

    // ---- expert loop: 2 chunks / 4 syncs per expert ----
    for (int e = 0; e < NEXP; e++) {
        float acc[2][8][4];
#pragma unroll
        for (int i = 0; i < 2; i++)
#pragma unroll
            for (int j = 0; j < 8; j++)
#pragma unroll
                for (int r = 0; r < 4; r++) acc[i][j][r] = 0.0f;

        // ===== GEMM1: 8 ksteps (k16 each), A = XF, weights buf0 =====
        CP_WAIT1(); __syncthreads();       // chunk 2e (W1_e) ready
#pragma unroll
        for (int k = 0; k < 8; k++) {
            unsigned a[2][4];
#pragma unroll
            for (int i = 0; i < 2; i++) {
                uint4 av = xfu[((t0 + i) * 8 + k) * 32 + lane];
                a[i][0] = av.x; a[i][1] = av.y; a[i][2] = av.z; a[i][3] = av.w;
            }
#pragma unroll
            for (int j = 0; j < 8; j++) {
                uint2 bv = wr0[(k * 16 + jb + j) * 32 + lane];
                unsigned b[2] = { bv.x, bv.y };
                mma_f16(acc[0][j], a[0], b);
                mma_f16(acc[1][j], a[1], b);
            }
        }
        __syncthreads();                   // buf0 consumed
        if (e < 9) {                       // issue chunk 2e+2 (W1_{e+1}) -> buf0
            const char* src = (const char*)g_wfrag + (size_t)(2 * e + 2) * 32768;
            uint32_t d = sb + WR_OFF;
#pragma unroll
            for (int i = 0; i < 8; i++) { uint32_t o = (uint32_t)(tid + i * 256) * 16u; cp16(d + o, src + o); }
        }
        CP_COMMIT();

        // ===== epilogue: h = fp16(mg * gelu(acc + b1)) -> HF in A-frag layout =====
        // thread owns all 4 components of 8 uint4 entries: t in {t0,t0+1}, k' in [kb2, kb2+4)
        {
            const float* b1 = b1s + e * 128;
#pragma unroll
            for (int i = 0; i < 2; i++) {
                int row0 = mrow + i * 16 + g;
                float w0 = (e < NRE) ? mgs[row0 * 8 + e] : 1.0f;
                float w1 = (e < NRE) ? mgs[(row0 + 8) * 8 + e] : 1.0f;
#pragma unroll
                for (int kp = 0; kp < 4; kp++) {
                    int jlo = 2 * kp, jhi = 2 * kp + 1;
                    int clo = 16 * (kb2 + kp) + 2 * c;       // lo col pair
                    float blo0 = b1[clo], blo1 = b1[clo + 1];
                    float bhi0 = b1[clo + 8], bhi1 = b1[clo + 9];
                    uint4 v;
                    v.x = h2u(__floats2half2_rn(w0 * gelu_f(acc[i][jlo][0] + blo0),
                                                w0 * gelu_f(acc[i][jlo][1] + blo1)));
                    v.y = h2u(__floats2half2_rn(w1 * gelu_f(acc[i][jlo][2] + blo0),
                                                w1 * gelu_f(acc[i][jlo][3] + blo1)));
                    v.z = h2u(__floats2half2_rn(w0 * gelu_f(acc[i][jhi][0] + bhi0),
                                                w0 * gelu_f(acc[i][jhi][1] + bhi1)));
                    v.w = h2u(__floats2half2_rn(w1 * gelu_f(acc[i][jhi][2] + bhi0),
                                                w1 * gelu_f(acc[i][jhi][3] + bhi1)));
                    hfu[((t0 + i) * 8 + kb2 + kp) * 32 + lane] = v;
                }
            }
        }
        CP_WAIT1(); __syncthreads();       // chunk 2e+1 (W2_e) ready AND h published

        // ===== GEMM2: 8 ksteps, A = HF (same shape as GEMM1), weights buf1 =====
#pragma unroll
        for (int k = 0; k < 8; k++) {
            unsigned a[2][4];
#pragma unroll
            for (int i = 0; i < 2; i++) {
                uint4 av = hfu[((t0 + i) * 8 + k) * 32 + lane];
                a[i][0] = av.x; a[i][1] = av.y; a[i][2] = av.z; a[i][3] = av.w;
            }
#pragma unroll
            for (int j = 0; j < 8; j++) {
                uint2 bv = wr1[(k * 16 + jb + j) * 32 + lane];
                unsigned b[2] = { bv.x, bv.y };
                mma_f16(facc[0][j], a[0], b);
                mma_f16(facc[1][j], a[1], b);
            }
        }
        __syncthreads();                   // buf1 consumed + all h reads done
        if (e < 9) {                       // issue chunk 2e+3 (W2_{e+1}) -> buf1
            const char* src = (const char*)g_wfrag + (size_t)(2 * e + 3) * 32768;
            uint32_t d = sb + WR_OFF + 32768u;
#pragma unroll
            for (int i = 0; i < 8; i++) { uint32_t o = (uint32_t)(tid + i * 256) * 16u; cp16(d + o, src + o); }
        }
        CP_COMMIT();
    }

    // ---- writeout: facc + rank-10 bias correction ----
#pragma unroll
    for (int i = 0; i < 2; i++)
#pragma unroll
        for (int j = 0; j < 8; j++)
#pragma unroll
            for (int rr = 0; rr < 2; rr++) {
                int row = mrow + i * 16 + g + rr * 8;
                int col = ncol + j * 8 + 2 * c;
                float v0 = facc[i][j][rr * 2 + 0];
                float v1 = facc[i][j][rr * 2 + 1];
#pragma unroll
                for (int e = 0; e < NRE; e++) {
                    float w = mgs[row * 8 + e];
                    v0 += w * b2s[e * 128 + col];
                    v1 += w * b2s[e * 128 + col + 1];
                }
                v0 += b2s[8 * 128 + col] + b2s[9 * 128 + col];
                v1 += b2s[8 * 128 + col + 1] + b2s[9 * 128 + col + 1];
                *reinterpret_cast<float2*>(out + (base + row) * 128 + col) = make_float2(v0, v1);
            }
}

extern "C" void kernel_launch(void* const* d_in, const int* in_sizes, int n_in,
                              void* d_out, int out_size) {
    const float* x   = (const float*)d_in[0];
    const float* Wr1 = (const float*)d_in[1];
    const float* br1 = (const float*)d_in[2];
    const float* Wr2 = (const float*)d_in[3];
    const float* br2 = (const float*)d_in[4];
    const float* We1 = (const float*)d_in[5];
    const float* be1 = (const float*)d_in[6];
    const float* We2 = (const float*)d_in[7];
    const float* be2 = (const float*)d_in[8];
    const float* Ws1 = (const float*)d_in[9];
    const float* bs1 = (const float*)d_in[10];
    const float* Ws2 = (const float*)d_in[11];
    const float* bs2 = (const float*)d_in[12];
    float* out = (float*)d_out;

    size_t prep_smem = 128 * XS * sizeof(float);
    cudaFuncSetAttribute(prep_kernel, cudaFuncAttributeMaxDynamicSharedMemorySize, (int)prep_smem);
    prep_kernel<<<20, 256, prep_smem>>>(We1, Ws1, We2, Ws2);

    int ntok = in_sizes[0] / 128;
    int grid = ntok / 128;
    cudaFuncSetAttribute(moe_kernel, cudaFuncAttributeMaxDynamicSharedMemorySize, SMEM_BYTES);
    moe_kernel<<<grid, 256, SMEM_BYTES>>>(x, Wr1, br1, Wr2, br2,
                                          be1, be2, bs1, bs2, out);
}

// round 14
// speedup vs baseline: 1.4755x; 1.4755x over previous
#include <cuda_runtime.h>
#include <cuda_fp16.h>
#include <cstdint>
#include <math.h>

#define NRE 8
#define NEXP 10
#define XS 132     // fp32 x staging row stride (floats)

// ---- dynamic smem byte offsets ----
#define XP_OFF   0          // 67584: fp32 x staging [128][132] (router + pack source)
#define XF_OFF   67584      // 32768: x A-frags fp16 [t8][k8][l32] uint4
#define HF_OFF   100352     // 32768: h A-frags fp16 [t8][k8][l32] uint4
#define WR_OFF   133120     // 65536: ring 2 x 32KB (buf0 = W1, buf1 = W2)
#define MGS_OFF  198656     // 4096
#define B1S_OFF  202752     // 5120
#define B2S_OFF  207872     // 5120
#define SMEM_BYTES 212992

// fp16 B-frag weight images: chunk c = 2e + {0:W1_e, 1:W2_e}, 32KB each.
// in-chunk: uint2 entry [(k8)*16 + j][l32] = { h2(W[16k+2c][n], W[16k+2c+1][n]),
//                                              h2(W[16k+2c+8][n], W[16k+2c+9][n]) }, n = 8j+g
__device__ __align__(16) uint2 g_wfrag[20 * 4096];

// ---------------- helpers ----------------
static __device__ __forceinline__ uint32_t s2u(const void* p) {
    uint32_t a;
    asm("{ .reg .u64 t; cvta.to.shared.u64 t, %1; cvt.u32.u64 %0, t; }" : "=r"(a) : "l"(p));
    return a;
}
static __device__ __forceinline__ unsigned h2u(__half2 h) {
    return *reinterpret_cast<unsigned*>(&h);
}
static __device__ __forceinline__ void mma_f16(float d[4], const unsigned a[4], const unsigned b[2]) {
    asm volatile(
        "mma.sync.aligned.m16n8k16.row.col.f32.f16.f16.f32 "
        "{%0,%1,%2,%3}, {%4,%5,%6,%7}, {%8,%9}, {%0,%1,%2,%3};"
        : "+f"(d[0]), "+f"(d[1]), "+f"(d[2]), "+f"(d[3])
        : "r"(a[0]), "r"(a[1]), "r"(a[2]), "r"(a[3]), "r"(b[0]), "r"(b[1]));
}
static __device__ __forceinline__ float gelu_tanh(float x) {
    float x3 = x * x * x;
    float inner = 0.7978845608028654f * (x + 0.044715f * x3);
    return 0.5f * x * (1.0f + tanhf(inner));
}
static __device__ __forceinline__ void cp16(uint32_t dst, const void* src) {
    asm volatile("cp.async.cg.shared.global [%0], [%1], 16;" :: "r"(dst), "l"(src) : "memory");
}
#define CP_COMMIT() asm volatile("cp.async.commit_group;" ::: "memory")
#define CP_WAIT1()  asm volatile("cp.async.wait_group 1;" ::: "memory")

// ============ prep: weights -> fp16 B-frag chunks (one matrix per block) ============
__global__ void __launch_bounds__(256, 1)
prep_kernel(const float* __restrict__ We1, const float* __restrict__ Ws1,
            const float* __restrict__ We2, const float* __restrict__ Ws2) {
    extern __shared__ float ws[];          // [128][132]
    int m = blockIdx.x;                    // 0..7 We1, 8..9 Ws1, 10..17 We2, 18..19 Ws2
    const float* W;
    int ee, isw2;
    if (m < 8)       { W = We1 + m * 16384;        ee = m;      isw2 = 0; }
    else if (m < 10) { W = Ws1 + (m - 8) * 16384;  ee = m;      isw2 = 0; }
    else if (m < 18) { W = We2 + (m - 10) * 16384; ee = m - 10; isw2 = 1; }
    else             { W = Ws2 + (m - 18) * 16384; ee = m - 10; isw2 = 1; }
    const int tid = threadIdx.x;
#pragma unroll
    for (int it = 0; it < 16; it++) {
        int idx = it * 256 + tid;
        int row = idx >> 5, c4 = (idx & 31) << 2;
        *reinterpret_cast<float4*>(ws + row * XS + c4) =
            *reinterpret_cast<const float4*>(W + row * 128 + c4);
    }
    __syncthreads();
    uint2* dst = g_wfrag + (size_t)(2 * ee + isw2) * 4096;
#pragma unroll
    for (int it = 0; it < 16; it++) {
        int i = it * 256 + tid;            // 0..4095: [k8][j16][l32]
        int l = i & 31, j = (i >> 5) & 15, k = i >> 9;
        int g = l >> 2, c = l & 3;
        int n = 8 * j + g;
        int r = 16 * k + 2 * c;
        __half2 lo = __floats2half2_rn(ws[r * XS + n],       ws[(r + 1) * XS + n]);
        __half2 hi = __floats2half2_rn(ws[(r + 8) * XS + n], ws[(r + 9) * XS + n]);
        uint2 o;
        o.x = h2u(lo);
        o.y = h2u(hi);
        dst[i] = o;
    }
}

// ============ main fused kernel ============
__global__ void __launch_bounds__(256, 1)
moe_kernel(const float* __restrict__ x,
           const float* __restrict__ Wr1, const float* __restrict__ br1,
           const float* __restrict__ Wr2, const float* __restrict__ br2,
           const float* __restrict__ be1, const float* __restrict__ be2,
           const float* __restrict__ bs1, const float* __restrict__ bs2,
           float* __restrict__ out) {
    extern __shared__ char smem[];
    const uint32_t sb = s2u(smem);
    float* xp  = (float*)(smem + XP_OFF);
    uint4* xfu = (uint4*)(smem + XF_OFF);
    uint4* hfu = (uint4*)(smem + HF_OFF);
    float* mgs = (float*)(smem + MGS_OFF);
    float* b1s = (float*)(smem + B1S_OFF);
    float* b2s = (float*)(smem + B2S_OFF);
    // router scratch overlays XF (packed only after router completes)
    float* rW1 = (float*)(smem + XF_OFF);
    float* rb1 = rW1 + 2048;
    float* rW2 = rW1 + 2064;
    float* rb2 = rW1 + 2192;
    float* rfb = rW1 + 2208;

    const int tid  = threadIdx.x;
    const int lane = tid & 31;
    const int wid  = tid >> 5;
    const int g    = lane >> 2;
    const int c    = lane & 3;
    const int t0   = (wid >> 1) * 2;       // first 16-row tile of this warp
    const int mrow = t0 * 16;
    const int jb   = (wid & 1) * 8;        // first n8 tile
    const int kb2  = (wid & 1) * 4;        // warp's k'-slice base for h A-frags
    const long base = (long)blockIdx.x * 128;

    // ---- issue first two 32KB chunks (W1_0 -> buf0, W2_0 -> buf1) ----
    {
        const char* src0 = (const char*)g_wfrag;
        uint32_t d0 = sb + WR_OFF, d1 = sb + WR_OFF + 32768u;
#pragma unroll
        for (int i = 0; i < 8; i++) { uint32_t o = (uint32_t)(tid + i * 256) * 16u; cp16(d0 + o, src0 + o); }
        CP_COMMIT();
#pragma unroll
        for (int i = 0; i < 8; i++) { uint32_t o = (uint32_t)(tid + i * 256) * 16u; cp16(d1 + o, src0 + 32768 + o); }
        CP_COMMIT();
    }

    // ---- stage x (fp32) + biases + router weights ----
#pragma unroll
    for (int it = 0; it < 16; it++) {
        int idx = it * 256 + tid;
        int row = idx >> 5, c4 = (idx & 31) << 2;
        float4 v = *reinterpret_cast<const float4*>(x + (base + row) * 128 + c4);
        *reinterpret_cast<float4*>(xp + row * XS + c4) = v;
    }
    for (int i = tid; i < 1280; i += 256) b1s[i] = (i < 1024) ? be1[i] : bs1[i - 1024];
    for (int i = tid; i < 1280; i += 256) b2s[i] = (i < 1024) ? be2[i] : bs2[i - 1024];
    for (int i = tid; i < 2048; i += 256) rW1[i] = Wr1[i];
    if (tid < 16)  rb1[tid] = br1[tid];
    if (tid < 128) rW2[tid] = Wr2[tid];
    if (tid < 8)   rb2[tid] = br2[tid];
    __syncthreads();

    // ---- router stage 1 (fp32, full precision) ----
    {
        int tok = tid & 127, jfb = (tid >> 7) * 8;
        float rf[8];
#pragma unroll
        for (int j = 0; j < 8; j++) rf[j] = rb1[jfb + j];
        for (int h = 0; h < 128; h++) {
            float xv = xp[tok * XS + h];
#pragma unroll
            for (int j = 0; j < 8; j++) rf[j] += xv * rW1[h * 16 + jfb + j];
        }
#pragma unroll
        for (int j = 0; j < 8; j++) rfb[tok * 16 + jfb + j] = fmaxf(rf[j], 0.0f);
    }
    __syncthreads();
    // ---- router stage 2: softmax -> threshold -> renorm ----
    if (tid < 128) {
        float lg[8];
#pragma unroll
        for (int e = 0; e < 8; e++) lg[e] = rb2[e];
#pragma unroll
        for (int r = 0; r < 16; r++) {
            float v = rfb[tid * 16 + r];
#pragma unroll
            for (int e = 0; e < 8; e++) lg[e] += v * rW2[r * 8 + e];
        }
        float mx = lg[0];
#pragma unroll
        for (int e = 1; e < 8; e++) mx = fmaxf(mx, lg[e]);
        float s = 0.0f, gt[8];
#pragma unroll
        for (int e = 0; e < 8; e++) { gt[e] = expf(lg[e] - mx); s += gt[e]; }
        float inv = 1.0f / s, msum = 0.0f;
#pragma unroll
        for (int e = 0; e < 8; e++) {
            float gv = gt[e] * inv;
            gv = (gv > 0.125f) ? gv : 0.0f;
            gt[e] = gv; msum += gv;
        }
        float innorm = 1.0f / (msum + 1e-8f);
#pragma unroll
        for (int e = 0; e < 8; e++) mgs[tid * 8 + e] = gt[e] * innorm;
    }
    __syncthreads();            // router scratch in XF now dead

    // ---- pack x -> XF fp16 A-frags [t8][k8][l32] uint4 ----
#pragma unroll
    for (int it = 0; it < 8; it++) {
        int i = it * 256 + tid;            // = (t*8+k)*32 + l
        int l = i & 31, k = (i >> 5) & 7, t = i >> 8;
        int gg = l >> 2, cc = l & 3;
        const float* p0 = xp + (16 * t + gg) * XS + 16 * k + 2 * cc;
        uint4 v;
        v.x = h2u(__floats2half2_rn(p0[0], p0[1]));                       // row g,   k 2c..2c+1
        v.y = h2u(__floats2half2_rn(p0[8 * XS], p0[8 * XS + 1]));         // row g+8
        v.z = h2u(__floats2half2_rn(p0[8], p0[9]));                       // row g,   k 2c+8..2c+9
        v.w = h2u(__floats2half2_rn(p0[8 * XS + 8], p0[8 * XS + 9]));     // row g+8
        xfu[i] = v;
    }
    __syncthreads();

    float facc[2][8][4];
#pragma unroll
    for (int i = 0; i < 2; i++)
#pragma unroll
        for (int j = 0; j < 8; j++)
#pragma unroll
            for (int r = 0; r < 4; r++) facc[i][j][r] = 0.0f;

    const uint2* wr0 = (const uint2*)(smem + WR_OFF);           // W1 chunk
    const uint2* wr1 = (const uint2*)(smem + WR_OFF + 32768);   // W2 chunk

    // ---- expert loop: 2 chunks / 4 syncs per expert ----
    for (int e = 0; e < NEXP; e++) {
        float acc[2][8][4];
#pragma unroll
        for (int i = 0; i < 2; i++)
#pragma unroll
            for (int j = 0; j < 8; j++)
#pragma unroll
                for (int r = 0; r < 4; r++) acc[i][j][r] = 0.0f;

        // ===== GEMM1: 8 ksteps (k16 each), A = XF, weights buf0 =====
        CP_WAIT1(); __syncthreads();       // chunk 2e (W1_e) ready
#pragma unroll
        for (int k = 0; k < 8; k++) {
            unsigned a[2][4];
#pragma unroll
            for (int i = 0; i < 2; i++) {
                uint4 av = xfu[((t0 + i) * 8 + k) * 32 + lane];
                a[i][0] = av.x; a[i][1] = av.y; a[i][2] = av.z; a[i][3] = av.w;
            }
#pragma unroll
            for (int j = 0; j < 8; j++) {
                uint2 bv = wr0[(k * 16 + jb + j) * 32 + lane];
                unsigned b[2] = { bv.x, bv.y };
                mma_f16(acc[0][j], a[0], b);
                mma_f16(acc[1][j], a[1], b);
            }
        }
        __syncthreads();                   // buf0 consumed
        if (e < 9) {                       // issue chunk 2e+2 (W1_{e+1}) -> buf0
            const char* src = (const char*)g_wfrag + (size_t)(2 * e + 2) * 32768;
            uint32_t d = sb + WR_OFF;
#pragma unroll
            for (int i = 0; i < 8; i++) { uint32_t o = (uint32_t)(tid + i * 256) * 16u; cp16(d + o, src + o); }
        }
        CP_COMMIT();

        // ===== epilogue: h = fp16(mg * gelu(acc + b1)) -> HF in A-frag layout =====
        // thread owns all 4 components of 8 uint4 entries: t in {t0,t0+1}, k' in [kb2, kb2+4)
        {
            const float* b1 = b1s + e * 128;
#pragma unroll
            for (int i = 0; i < 2; i++) {
                int row0 = mrow + i * 16 + g;
                float w0 = (e < NRE) ? mgs[row0 * 8 + e] : 1.0f;
                float w1 = (e < NRE) ? mgs[(row0 + 8) * 8 + e] : 1.0f;
#pragma unroll
                for (int kp = 0; kp < 4; kp++) {
                    int jlo = 2 * kp, jhi = 2 * kp + 1;
                    int clo = 16 * (kb2 + kp) + 2 * c;       // lo col pair
                    float blo0 = b1[clo], blo1 = b1[clo + 1];
                    float bhi0 = b1[clo + 8], bhi1 = b1[clo + 9];
                    uint4 v;
                    v.x = h2u(__floats2half2_rn(w0 * gelu_tanh(acc[i][jlo][0] + blo0),
                                                w0 * gelu_tanh(acc[i][jlo][1] + blo1)));
                    v.y = h2u(__floats2half2_rn(w1 * gelu_tanh(acc[i][jlo][2] + blo0),
                                                w1 * gelu_tanh(acc[i][jlo][3] + blo1)));
                    v.z = h2u(__floats2half2_rn(w0 * gelu_tanh(acc[i][jhi][0] + bhi0),
                                                w0 * gelu_tanh(acc[i][jhi][1] + bhi1)));
                    v.w = h2u(__floats2half2_rn(w1 * gelu_tanh(acc[i][jhi][2] + bhi0),
                                                w1 * gelu_tanh(acc[i][jhi][3] + bhi1)));
                    hfu[((t0 + i) * 8 + kb2 + kp) * 32 + lane] = v;
                }
            }
        }
        CP_WAIT1(); __syncthreads();       // chunk 2e+1 (W2_e) ready AND h published

        // ===== GEMM2: 8 ksteps, A = HF (same shape as GEMM1), weights buf1 =====
#pragma unroll
        for (int k = 0; k < 8; k++) {
            unsigned a[2][4];
#pragma unroll
            for (int i = 0; i < 2; i++) {
                uint4 av = hfu[((t0 + i) * 8 + k) * 32 + lane];
                a[i][0] = av.x; a[i][1] = av.y; a[i][2] = av.z; a[i][3] = av.w;
            }
#pragma unroll
            for (int j = 0; j < 8; j++) {
                uint2 bv = wr1[(k * 16 + jb + j) * 32 + lane];
                unsigned b[2] = { bv.x, bv.y };
                mma_f16(facc[0][j], a[0], b);
                mma_f16(facc[1][j], a[1], b);
            }
        }
        __syncthreads();                   // buf1 consumed + all h reads done
        if (e < 9) {                       // issue chunk 2e+3 (W2_{e+1}) -> buf1
            const char* src = (const char*)g_wfrag + (size_t)(2 * e + 3) * 32768;
            uint32_t d = sb + WR_OFF + 32768u;
#pragma unroll
            for (int i = 0; i < 8; i++) { uint32_t o = (uint32_t)(tid + i * 256) * 16u; cp16(d + o, src + o); }
        }
        CP_COMMIT();
    }

    // ---- writeout: facc + rank-10 bias correction ----
#pragma unroll
    for (int i = 0; i < 2; i++)
#pragma unroll
        for (int j = 0; j < 8; j++)
#pragma unroll
            for (int rr = 0; rr < 2; rr++) {
                int row = mrow + i * 16 + g + rr * 8;
                int col = jb * 8 + j * 8 + 2 * c;
                float v0 = facc[i][j][rr * 2 + 0];
                float v1 = facc[i][j][rr * 2 + 1];
#pragma unroll
                for (int e = 0; e < NRE; e++) {
                    float w = mgs[row * 8 + e];
                    v0 += w * b2s[e * 128 + col];
                    v1 += w * b2s[e * 128 + col + 1];
                }
                v0 += b2s[8 * 128 + col] + b2s[9 * 128 + col];
                v1 += b2s[8 * 128 + col + 1] + b2s[9 * 128 + col + 1];
                *reinterpret_cast<float2*>(out + (base + row) * 128 + col) = make_float2(v0, v1);
            }
}

extern "C" void kernel_launch(void* const* d_in, const int* in_sizes, int n_in,
                              void* d_out, int out_size) {
    const float* x   = (const float*)d_in[0];
    const float* Wr1 = (const float*)d_in[1];
    const float* br1 = (const float*)d_in[2];
    const float* Wr2 = (const float*)d_in[3];
    const float* br2 = (const float*)d_in[4];
    const float* We1 = (const float*)d_in[5];
    const float* be1 = (const float*)d_in[6];
    const float* We2 = (const float*)d_in[7];
    const float* be2 = (const float*)d_in[8];
    const float* Ws1 = (const float*)d_in[9];
    const float* bs1 = (const float*)d_in[10];
    const float* Ws2 = (const float*)d_in[11];
    const float* bs2 = (const float*)d_in[12];
    float* out = (float*)d_out;

    size_t prep_smem = 128 * XS * sizeof(float);
    cudaFuncSetAttribute(prep_kernel, cudaFuncAttributeMaxDynamicSharedMemorySize, (int)prep_smem);
    prep_kernel<<<20, 256, prep_smem>>>(We1, Ws1, We2, Ws2);

    int ntok = in_sizes[0] / 128;
    int grid = ntok / 128;
    cudaFuncSetAttribute(moe_kernel, cudaFuncAttributeMaxDynamicSharedMemorySize, SMEM_BYTES);
    moe_kernel<<<grid, 256, SMEM_BYTES>>>(x, Wr1, br1, Wr2, br2,
                                          be1, be2, bs1, bs2, out);
}

// round 15
// speedup vs baseline: 1.5084x; 1.0223x over previous
#include <cuda_runtime.h>
#include <cuda_fp16.h>
#include <cstdint>
#include <math.h>

#define NRE 8
#define NEXP 10
#define XS 132     // fp32 x staging row stride (floats)

// ---- dynamic smem byte offsets ----
// XP region [0, 67584) holds fp32 x staging during prologue; after the x-pack
// it is DEAD and weight ring buffers 2/3 overlay its first 65536 bytes.
#define XP_OFF   0          // 67584: fp32 x staging [128][132] / later ring buf2+buf3
#define XF_OFF   67584      // 32768: x A-frags fp16 [t8][k8][l32] uint4
#define HF_OFF   100352     // 32768: h A-frags fp16 [t8][k8][l32] uint4
#define WR_OFF   133120     // 65536: ring buf0 + buf1
#define MGS_OFF  198656     // 4096
#define B1S_OFF  202752     // 5120
#define B2S_OFF  207872     // 5120
#define SMEM_BYTES 212992

// fp16 B-frag weight images: chunk s = 2e + {0:W1_e, 1:W2_e}, 32KB each (20 chunks).
// in-chunk: uint2 entry [(k8)*16 + j][l32] = { h2(W[16k+2c][n], W[16k+2c+1][n]),
//                                              h2(W[16k+2c+8][n], W[16k+2c+9][n]) }, n = 8j+g
__device__ __align__(16) uint2 g_wfrag[20 * 4096];

// ---------------- helpers ----------------
static __device__ __forceinline__ uint32_t s2u(const void* p) {
    uint32_t a;
    asm("{ .reg .u64 t; cvta.to.shared.u64 t, %1; cvt.u32.u64 %0, t; }" : "=r"(a) : "l"(p));
    return a;
}
static __device__ __forceinline__ unsigned h2u(__half2 h) {
    return *reinterpret_cast<unsigned*>(&h);
}
static __device__ __forceinline__ void mma_f16(float d[4], const unsigned a[4], const unsigned b[2]) {
    asm volatile(
        "mma.sync.aligned.m16n8k16.row.col.f32.f16.f16.f32 "
        "{%0,%1,%2,%3}, {%4,%5,%6,%7}, {%8,%9}, {%0,%1,%2,%3};"
        : "+f"(d[0]), "+f"(d[1]), "+f"(d[2]), "+f"(d[3])
        : "r"(a[0]), "r"(a[1]), "r"(a[2]), "r"(a[3]), "r"(b[0]), "r"(b[1]));
}
static __device__ __forceinline__ float gelu_tanh(float x) {
    float x3 = x * x * x;
    float inner = 0.7978845608028654f * (x + 0.044715f * x3);
    return 0.5f * x * (1.0f + tanhf(inner));
}
static __device__ __forceinline__ void cp16(uint32_t dst, const void* src) {
    asm volatile("cp.async.cg.shared.global [%0], [%1], 16;" :: "r"(dst), "l"(src) : "memory");
}
#define CP_COMMIT() asm volatile("cp.async.commit_group;" ::: "memory")
#define CP_WAIT2()  asm volatile("cp.async.wait_group 2;" ::: "memory")

// ============ prep: weights -> fp16 B-frag chunks (one matrix per block) ============
__global__ void __launch_bounds__(256, 1)
prep_kernel(const float* __restrict__ We1, const float* __restrict__ Ws1,
            const float* __restrict__ We2, const float* __restrict__ Ws2) {
    extern __shared__ float ws[];          // [128][132]
    int m = blockIdx.x;                    // 0..7 We1, 8..9 Ws1, 10..17 We2, 18..19 Ws2
    const float* W;
    int ee, isw2;
    if (m < 8)       { W = We1 + m * 16384;        ee = m;      isw2 = 0; }
    else if (m < 10) { W = Ws1 + (m - 8) * 16384;  ee = m;      isw2 = 0; }
    else if (m < 18) { W = We2 + (m - 10) * 16384; ee = m - 10; isw2 = 1; }
    else             { W = Ws2 + (m - 18) * 16384; ee = m - 10; isw2 = 1; }
    const int tid = threadIdx.x;
#pragma unroll
    for (int it = 0; it < 16; it++) {
        int idx = it * 256 + tid;
        int row = idx >> 5, c4 = (idx & 31) << 2;
        *reinterpret_cast<float4*>(ws + row * XS + c4) =
            *reinterpret_cast<const float4*>(W + row * 128 + c4);
    }
    __syncthreads();
    uint2* dst = g_wfrag + (size_t)(2 * ee + isw2) * 4096;
#pragma unroll
    for (int it = 0; it < 16; it++) {
        int i = it * 256 + tid;            // 0..4095: [k8][j16][l32]
        int l = i & 31, j = (i >> 5) & 15, k = i >> 9;
        int g = l >> 2, c = l & 3;
        int n = 8 * j + g;
        int r = 16 * k + 2 * c;
        __half2 lo = __floats2half2_rn(ws[r * XS + n],       ws[(r + 1) * XS + n]);
        __half2 hi = __floats2half2_rn(ws[(r + 8) * XS + n], ws[(r + 9) * XS + n]);
        uint2 o;
        o.x = h2u(lo);
        o.y = h2u(hi);
        dst[i] = o;
    }
}

// ============ main fused kernel: 4-deep weight ring, one sync per phase ============
__global__ void __launch_bounds__(256, 1)
moe_kernel(const float* __restrict__ x,
           const float* __restrict__ Wr1, const float* __restrict__ br1,
           const float* __restrict__ Wr2, const float* __restrict__ br2,
           const float* __restrict__ be1, const float* __restrict__ be2,
           const float* __restrict__ bs1, const float* __restrict__ bs2,
           float* __restrict__ out) {
    extern __shared__ char smem[];
    const uint32_t sb = s2u(smem);
    float* xp  = (float*)(smem + XP_OFF);
    uint4* xfu = (uint4*)(smem + XF_OFF);
    uint4* hfu = (uint4*)(smem + HF_OFF);
    float* mgs = (float*)(smem + MGS_OFF);
    float* b1s = (float*)(smem + B1S_OFF);
    float* b2s = (float*)(smem + B2S_OFF);
    // router scratch overlays XF (packed only after router completes)
    float* rW1 = (float*)(smem + XF_OFF);
    float* rb1 = rW1 + 2048;
    float* rW2 = rW1 + 2064;
    float* rb2 = rW1 + 2192;
    float* rfb = rW1 + 2208;

    const int tid  = threadIdx.x;
    const int lane = tid & 31;
    const int wid  = tid >> 5;
    const int g    = lane >> 2;
    const int c    = lane & 3;
    const int t0   = (wid >> 1) * 2;       // first 16-row tile of this warp
    const int mrow = t0 * 16;
    const int jb   = (wid & 1) * 8;        // first n8 tile
    const int kb2  = (wid & 1) * 4;        // warp's k'-slice base for h A-frags
    const long base = (long)blockIdx.x * 128;

    // ring buffer idx -> smem byte offset (buf0/1 in WR region, buf2/3 overlay XP)
    auto bufoff = [&](int idx) -> uint32_t {
        return (idx < 2) ? (uint32_t)WR_OFF + (uint32_t)idx * 32768u
                         : (uint32_t)(idx - 2) * 32768u;
    };
    auto issue = [&](int s) {
        uint32_t d = sb + bufoff(s & 3);
        const char* src = (const char*)g_wfrag + (size_t)s * 32768;
#pragma unroll
        for (int i = 0; i < 8; i++) {
            uint32_t o = (uint32_t)(tid + i * 256) * 16u;
            cp16(d + o, src + o);
        }
    };

    // ---- prologue: chunks 0,1 -> buf0,buf1 (WR region; safe before staging) ----
    issue(0); CP_COMMIT();
    issue(1); CP_COMMIT();

    // ---- stage x (fp32) + biases + router weights ----
#pragma unroll
    for (int it = 0; it < 16; it++) {
        int idx = it * 256 + tid;
        int row = idx >> 5, c4 = (idx & 31) << 2;
        float4 v = *reinterpret_cast<const float4*>(x + (base + row) * 128 + c4);
        *reinterpret_cast<float4*>(xp + row * XS + c4) = v;
    }
    for (int i = tid; i < 1280; i += 256) b1s[i] = (i < 1024) ? be1[i] : bs1[i - 1024];
    for (int i = tid; i < 1280; i += 256) b2s[i] = (i < 1024) ? be2[i] : bs2[i - 1024];
    for (int i = tid; i < 2048; i += 256) rW1[i] = Wr1[i];
    if (tid < 16)  rb1[tid] = br1[tid];
    if (tid < 128) rW2[tid] = Wr2[tid];
    if (tid < 8)   rb2[tid] = br2[tid];
    __syncthreads();

    // ---- router stage 1 (fp32, full precision) ----
    {
        int tok = tid & 127, jfb = (tid >> 7) * 8;
        float rf[8];
#pragma unroll
        for (int j = 0; j < 8; j++) rf[j] = rb1[jfb + j];
        for (int h = 0; h < 128; h++) {
            float xv = xp[tok * XS + h];
#pragma unroll
            for (int j = 0; j < 8; j++) rf[j] += xv * rW1[h * 16 + jfb + j];
        }
#pragma unroll
        for (int j = 0; j < 8; j++) rfb[tok * 16 + jfb + j] = fmaxf(rf[j], 0.0f);
    }
    __syncthreads();
    // ---- router stage 2: softmax -> threshold -> renorm ----
    if (tid < 128) {
        float lg[8];
#pragma unroll
        for (int e = 0; e < 8; e++) lg[e] = rb2[e];
#pragma unroll
        for (int r = 0; r < 16; r++) {
            float v = rfb[tid * 16 + r];
#pragma unroll
            for (int e = 0; e < 8; e++) lg[e] += v * rW2[r * 8 + e];
        }
        float mx = lg[0];
#pragma unroll
        for (int e = 1; e < 8; e++) mx = fmaxf(mx, lg[e]);
        float s = 0.0f, gt[8];
#pragma unroll
        for (int e = 0; e < 8; e++) { gt[e] = expf(lg[e] - mx); s += gt[e]; }
        float inv = 1.0f / s, msum = 0.0f;
#pragma unroll
        for (int e = 0; e < 8; e++) {
            float gv = gt[e] * inv;
            gv = (gv > 0.125f) ? gv : 0.0f;
            gt[e] = gv; msum += gv;
        }
        float innorm = 1.0f / (msum + 1e-8f);
#pragma unroll
        for (int e = 0; e < 8; e++) mgs[tid * 8 + e] = gt[e] * innorm;
    }
    __syncthreads();            // router scratch in XF now dead

    // ---- pack x -> XF fp16 A-frags [t8][k8][l32] uint4 ----
#pragma unroll
    for (int it = 0; it < 8; it++) {
        int i = it * 256 + tid;            // = (t*8+k)*32 + l
        int l = i & 31, k = (i >> 5) & 7, t = i >> 8;
        int gg = l >> 2, cc = l & 3;
        const float* p0 = xp + (16 * t + gg) * XS + 16 * k + 2 * cc;
        uint4 v;
        v.x = h2u(__floats2half2_rn(p0[0], p0[1]));                       // row g,   k 2c..2c+1
        v.y = h2u(__floats2half2_rn(p0[8 * XS], p0[8 * XS + 1]));         // row g+8
        v.z = h2u(__floats2half2_rn(p0[8], p0[9]));                       // row g,   k 2c+8..2c+9
        v.w = h2u(__floats2half2_rn(p0[8 * XS + 8], p0[8 * XS + 9]));     // row g+8
        xfu[i] = v;
    }
    __syncthreads();            // XP now dead: ring buf2/buf3 may overlay it

    float facc[2][8][4];
#pragma unroll
    for (int i = 0; i < 2; i++)
#pragma unroll
        for (int j = 0; j < 8; j++)
#pragma unroll
            for (int r = 0; r < 4; r++) facc[i][j][r] = 0.0f;

    // ---- expert loop: 2 phases per expert, ONE sync per phase ----
    for (int e = 0; e < NEXP; e++) {
        float acc[2][8][4];
#pragma unroll
        for (int i = 0; i < 2; i++)
#pragma unroll
            for (int j = 0; j < 8; j++)
#pragma unroll
                for (int r = 0; r < 4; r++) acc[i][j][r] = 0.0f;

        // ===== phase s = 2e: GEMM1 from buf[(2e)&3] =====
        {
            int s = 2 * e;
            if (s + 2 < 20) issue(s + 2);
            CP_COMMIT();
            CP_WAIT2(); __syncthreads();   // chunk s ready; prior-phase reads all done
            const uint2* wr = (const uint2*)(smem + bufoff(s & 3));
#pragma unroll
            for (int k = 0; k < 8; k++) {
                unsigned a[2][4];
#pragma unroll
                for (int i = 0; i < 2; i++) {
                    uint4 av = xfu[((t0 + i) * 8 + k) * 32 + lane];
                    a[i][0] = av.x; a[i][1] = av.y; a[i][2] = av.z; a[i][3] = av.w;
                }
#pragma unroll
                for (int j = 0; j < 8; j++) {
                    uint2 bv = wr[(k * 16 + jb + j) * 32 + lane];
                    unsigned b[2] = { bv.x, bv.y };
                    mma_f16(acc[0][j], a[0], b);
                    mma_f16(acc[1][j], a[1], b);
                }
            }
        }

        // ===== epilogue: h = fp16(mg * gelu(acc + b1)) -> HF in A-frag layout =====
        {
            const float* b1 = b1s + e * 128;
#pragma unroll
            for (int i = 0; i < 2; i++) {
                int row0 = mrow + i * 16 + g;
                float w0 = (e < NRE) ? mgs[row0 * 8 + e] : 1.0f;
                float w1 = (e < NRE) ? mgs[(row0 + 8) * 8 + e] : 1.0f;
#pragma unroll
                for (int kp = 0; kp < 4; kp++) {
                    int jlo = 2 * kp, jhi = 2 * kp + 1;
                    int clo = 16 * (kb2 + kp) + 2 * c;
                    float blo0 = b1[clo], blo1 = b1[clo + 1];
                    float bhi0 = b1[clo + 8], bhi1 = b1[clo + 9];
                    uint4 v;
                    v.x = h2u(__floats2half2_rn(w0 * gelu_tanh(acc[i][jlo][0] + blo0),
                                                w0 * gelu_tanh(acc[i][jlo][1] + blo1)));
                    v.y = h2u(__floats2half2_rn(w1 * gelu_tanh(acc[i][jlo][2] + blo0),
                                                w1 * gelu_tanh(acc[i][jlo][3] + blo1)));
                    v.z = h2u(__floats2half2_rn(w0 * gelu_tanh(acc[i][jhi][0] + bhi0),
                                                w0 * gelu_tanh(acc[i][jhi][1] + bhi1)));
                    v.w = h2u(__floats2half2_rn(w1 * gelu_tanh(acc[i][jhi][2] + bhi0),
                                                w1 * gelu_tanh(acc[i][jhi][3] + bhi1)));
                    hfu[((t0 + i) * 8 + kb2 + kp) * 32 + lane] = v;
                }
            }
        }

        // ===== phase s = 2e+1: GEMM2 from buf[(2e+1)&3] (sync also publishes h) =====
        {
            int s = 2 * e + 1;
            if (s + 2 < 20) issue(s + 2);
            CP_COMMIT();
            CP_WAIT2(); __syncthreads();   // chunk s ready AND hfu published
            const uint2* wr = (const uint2*)(smem + bufoff(s & 3));
#pragma unroll
            for (int k = 0; k < 8; k++) {
                unsigned a[2][4];
#pragma unroll
                for (int i = 0; i < 2; i++) {
                    uint4 av = hfu[((t0 + i) * 8 + k) * 32 + lane];
                    a[i][0] = av.x; a[i][1] = av.y; a[i][2] = av.z; a[i][3] = av.w;
                }
#pragma unroll
                for (int j = 0; j < 8; j++) {
                    uint2 bv = wr[(k * 16 + jb + j) * 32 + lane];
                    unsigned b[2] = { bv.x, bv.y };
                    mma_f16(facc[0][j], a[0], b);
                    mma_f16(facc[1][j], a[1], b);
                }
            }
        }
    }

    // ---- writeout: facc + rank-10 bias correction ----
#pragma unroll
    for (int i = 0; i < 2; i++)
#pragma unroll
        for (int j = 0; j < 8; j++)
#pragma unroll
            for (int rr = 0; rr < 2; rr++) {
                int row = mrow + i * 16 + g + rr * 8;
                int col = jb * 8 + j * 8 + 2 * c;
                float v0 = facc[i][j][rr * 2 + 0];
                float v1 = facc[i][j][rr * 2 + 1];
#pragma unroll
                for (int e = 0; e < NRE; e++) {
                    float w = mgs[row * 8 + e];
                    v0 += w * b2s[e * 128 + col];
                    v1 += w * b2s[e * 128 + col + 1];
                }
                v0 += b2s[8 * 128 + col] + b2s[9 * 128 + col];
                v1 += b2s[8 * 128 + col + 1] + b2s[9 * 128 + col + 1];
                *reinterpret_cast<float2*>(out + (base + row) * 128 + col) = make_float2(v0, v1);
            }
}

extern "C" void kernel_launch(void* const* d_in, const int* in_sizes, int n_in,
                              void* d_out, int out_size) {
    const float* x   = (const float*)d_in[0];
    const float* Wr1 = (const float*)d_in[1];
    const float* br1 = (const float*)d_in[2];
    const float* Wr2 = (const float*)d_in[3];
    const float* br2 = (const float*)d_in[4];
    const float* We1 = (const float*)d_in[5];
    const float* be1 = (const float*)d_in[6];
    const float* We2 = (const float*)d_in[7];
    const float* be2 = (const float*)d_in[8];
    const float* Ws1 = (const float*)d_in[9];
    const float* bs1 = (const float*)d_in[10];
    const float* Ws2 = (const float*)d_in[11];
    const float* bs2 = (const float*)d_in[12];
    float* out = (float*)d_out;

    size_t prep_smem = 128 * XS * sizeof(float);
    cudaFuncSetAttribute(prep_kernel, cudaFuncAttributeMaxDynamicSharedMemorySize, (int)prep_smem);
    prep_kernel<<<20, 256, prep_smem>>>(We1, Ws1, We2, Ws2);

    int ntok = in_sizes[0] / 128;
    int grid = ntok / 128;
    cudaFuncSetAttribute(moe_kernel, cudaFuncAttributeMaxDynamicSharedMemorySize, SMEM_BYTES);
    moe_kernel<<<grid, 256, SMEM_BYTES>>>(x, Wr1, br1, Wr2, br2,
                                          be1, be2, bs1, bs2, out);
}

// round 16
// speedup vs baseline: 1.8482x; 1.2253x over previous
#include <cuda_runtime.h>
#include <cuda_fp16.h>
#include <cstdint>
#include <math.h>

#define NRE 8
#define NEXP 10
#define XS 132     // fp32 x staging row stride (floats)

// ---- dynamic smem byte offsets ----
// XP region [0, 67584) holds fp32 x staging during prologue; after the x-pack
// it is DEAD and weight ring buffers 2/3 overlay its first 65536 bytes.
#define XP_OFF   0          // 67584: fp32 x staging [128][132] / later ring buf2+buf3
#define XF_OFF   67584      // 32768: x A-frags fp16 [t8][k8][l32] uint4
#define HF_OFF   100352     // 32768: h A-frags fp16 [t8][k8][l32] uint4
#define WR_OFF   133120     // 65536: ring buf0 + buf1
#define MGS_OFF  198656     // 4096
#define B1S_OFF  202752     // 5120
#define B2S_OFF  207872     // 5120
#define SMEM_BYTES 212992

// fp16 B-frag weight images: chunk s = 2e + {0:W1_e, 1:W2_e}, 32KB each (20 chunks).
// in-chunk: uint2 entry [(k8)*16 + j][l32] = { h2(W[16k+2c][n], W[16k+2c+1][n]),
//                                              h2(W[16k+2c+8][n], W[16k+2c+9][n]) }, n = 8j+g
__device__ __align__(16) uint2 g_wfrag[20 * 4096];

// ---------------- helpers ----------------
static __device__ __forceinline__ uint32_t s2u(const void* p) {
    uint32_t a;
    asm("{ .reg .u64 t; cvta.to.shared.u64 t, %1; cvt.u32.u64 %0, t; }" : "=r"(a) : "l"(p));
    return a;
}
static __device__ __forceinline__ unsigned h2u(__half2 h) {
    return *reinterpret_cast<unsigned*>(&h);
}
static __device__ __forceinline__ void mma_f16(float d[4], const unsigned a[4], const unsigned b[2]) {
    asm volatile(
        "mma.sync.aligned.m16n8k16.row.col.f32.f16.f16.f32 "
        "{%0,%1,%2,%3}, {%4,%5,%6,%7}, {%8,%9}, {%0,%1,%2,%3};"
        : "+f"(d[0]), "+f"(d[1]), "+f"(d[2]), "+f"(d[3])
        : "r"(a[0]), "r"(a[1]), "r"(a[2]), "r"(a[3]), "r"(b[0]), "r"(b[1]));
}
// gelu with single-MUFU hardware tanh (sm_75+): ~5 instrs vs ~16 for libm tanhf.
static __device__ __forceinline__ float gelu_tanh(float x) {
    float u = 0.7978845608028654f * (x + 0.044715f * x * x * x);
    float t;
    asm("tanh.approx.f32 %0, %1;" : "=f"(t) : "f"(u));
    return 0.5f * x * (1.0f + t);
}
static __device__ __forceinline__ void cp16(uint32_t dst, const void* src) {
    asm volatile("cp.async.cg.shared.global [%0], [%1], 16;" :: "r"(dst), "l"(src) : "memory");
}
#define CP_COMMIT() asm volatile("cp.async.commit_group;" ::: "memory")
#define CP_WAIT2()  asm volatile("cp.async.wait_group 2;" ::: "memory")

// ============ prep: weights -> fp16 B-frag chunks (one matrix per block) ============
__global__ void __launch_bounds__(256, 1)
prep_kernel(const float* __restrict__ We1, const float* __restrict__ Ws1,
            const float* __restrict__ We2, const float* __restrict__ Ws2) {
    extern __shared__ float ws[];          // [128][132]
    int m = blockIdx.x;                    // 0..7 We1, 8..9 Ws1, 10..17 We2, 18..19 Ws2
    const float* W;
    int ee, isw2;
    if (m < 8)       { W = We1 + m * 16384;        ee = m;      isw2 = 0; }
    else if (m < 10) { W = Ws1 + (m - 8) * 16384;  ee = m;      isw2 = 0; }
    else if (m < 18) { W = We2 + (m - 10) * 16384; ee = m - 10; isw2 = 1; }
    else             { W = Ws2 + (m - 18) * 16384; ee = m - 10; isw2 = 1; }
    const int tid = threadIdx.x;
#pragma unroll
    for (int it = 0; it < 16; it++) {
        int idx = it * 256 + tid;
        int row = idx >> 5, c4 = (idx & 31) << 2;
        *reinterpret_cast<float4*>(ws + row * XS + c4) =
            *reinterpret_cast<const float4*>(W + row * 128 + c4);
    }
    __syncthreads();
    uint2* dst = g_wfrag + (size_t)(2 * ee + isw2) * 4096;
#pragma unroll
    for (int it = 0; it < 16; it++) {
        int i = it * 256 + tid;            // 0..4095: [k8][j16][l32]
        int l = i & 31, j = (i >> 5) & 15, k = i >> 9;
        int g = l >> 2, c = l & 3;
        int n = 8 * j + g;
        int r = 16 * k + 2 * c;
        __half2 lo = __floats2half2_rn(ws[r * XS + n],       ws[(r + 1) * XS + n]);
        __half2 hi = __floats2half2_rn(ws[(r + 8) * XS + n], ws[(r + 9) * XS + n]);
        uint2 o;
        o.x = h2u(lo);
        o.y = h2u(hi);
        dst[i] = o;
    }
}

// ============ main fused kernel: 4-deep weight ring, one sync per phase ============
__global__ void __launch_bounds__(256, 1)
moe_kernel(const float* __restrict__ x,
           const float* __restrict__ Wr1, const float* __restrict__ br1,
           const float* __restrict__ Wr2, const float* __restrict__ br2,
           const float* __restrict__ be1, const float* __restrict__ be2,
           const float* __restrict__ bs1, const float* __restrict__ bs2,
           float* __restrict__ out) {
    extern __shared__ char smem[];
    const uint32_t sb = s2u(smem);
    float* xp  = (float*)(smem + XP_OFF);
    uint4* xfu = (uint4*)(smem + XF_OFF);
    uint4* hfu = (uint4*)(smem + HF_OFF);
    float* mgs = (float*)(smem + MGS_OFF);
    float* b1s = (float*)(smem + B1S_OFF);
    float* b2s = (float*)(smem + B2S_OFF);
    // router scratch overlays XF (packed only after router completes)
    float* rW1 = (float*)(smem + XF_OFF);
    float* rb1 = rW1 + 2048;
    float* rW2 = rW1 + 2064;
    float* rb2 = rW1 + 2192;
    float* rfb = rW1 + 2208;

    const int tid  = threadIdx.x;
    const int lane = tid & 31;
    const int wid  = tid >> 5;
    const int g    = lane >> 2;
    const int c    = lane & 3;
    const int t0   = (wid >> 1) * 2;       // first 16-row tile of this warp
    const int mrow = t0 * 16;
    const int jb   = (wid & 1) * 8;        // first n8 tile
    const int kb2  = (wid & 1) * 4;        // warp's k'-slice base for h A-frags
    const long base = (long)blockIdx.x * 128;

    // ring buffer idx -> smem byte offset (buf0/1 in WR region, buf2/3 overlay XP)
    auto bufoff = [&](int idx) -> uint32_t {
        return (idx < 2) ? (uint32_t)WR_OFF + (uint32_t)idx * 32768u
                         : (uint32_t)(idx - 2) * 32768u;
    };
    auto issue = [&](int s) {
        uint32_t d = sb + bufoff(s & 3);
        const char* src = (const char*)g_wfrag + (size_t)s * 32768;
#pragma unroll
        for (int i = 0; i < 8; i++) {
            uint32_t o = (uint32_t)(tid + i * 256) * 16u;
            cp16(d + o, src + o);
        }
    };

    // ---- prologue: chunks 0,1 -> buf0,buf1 (WR region; safe before staging) ----
    issue(0); CP_COMMIT();
    issue(1); CP_COMMIT();

    // ---- stage x (fp32) + biases + router weights ----
#pragma unroll
    for (int it = 0; it < 16; it++) {
        int idx = it * 256 + tid;
        int row = idx >> 5, c4 = (idx & 31) << 2;
        float4 v = *reinterpret_cast<const float4*>(x + (base + row) * 128 + c4);
        *reinterpret_cast<float4*>(xp + row * XS + c4) = v;
    }
    for (int i = tid; i < 1280; i += 256) b1s[i] = (i < 1024) ? be1[i] : bs1[i - 1024];
    for (int i = tid; i < 1280; i += 256) b2s[i] = (i < 1024) ? be2[i] : bs2[i - 1024];
    for (int i = tid; i < 2048; i += 256) rW1[i] = Wr1[i];
    if (tid < 16)  rb1[tid] = br1[tid];
    if (tid < 128) rW2[tid] = Wr2[tid];
    if (tid < 8)   rb2[tid] = br2[tid];
    __syncthreads();

    // ---- router stage 1 (fp32, full precision) ----
    {
        int tok = tid & 127, jfb = (tid >> 7) * 8;
        float rf[8];
#pragma unroll
        for (int j = 0; j < 8; j++) rf[j] = rb1[jfb + j];
        for (int h = 0; h < 128; h++) {
            float xv = xp[tok * XS + h];
#pragma unroll
            for (int j = 0; j < 8; j++) rf[j] += xv * rW1[h * 16 + jfb + j];
        }
#pragma unroll
        for (int j = 0; j < 8; j++) rfb[tok * 16 + jfb + j] = fmaxf(rf[j], 0.0f);
    }
    __syncthreads();
    // ---- router stage 2: softmax -> threshold -> renorm ----
    if (tid < 128) {
        float lg[8];
#pragma unroll
        for (int e = 0; e < 8; e++) lg[e] = rb2[e];
#pragma unroll
        for (int r = 0; r < 16; r++) {
            float v = rfb[tid * 16 + r];
#pragma unroll
            for (int e = 0; e < 8; e++) lg[e] += v * rW2[r * 8 + e];
        }
        float mx = lg[0];
#pragma unroll
        for (int e = 1; e < 8; e++) mx = fmaxf(mx, lg[e]);
        float s = 0.0f, gt[8];
#pragma unroll
        for (int e = 0; e < 8; e++) { gt[e] = expf(lg[e] - mx); s += gt[e]; }
        float inv = 1.0f / s, msum = 0.0f;
#pragma unroll
        for (int e = 0; e < 8; e++) {
            float gv = gt[e] * inv;
            gv = (gv > 0.125f) ? gv : 0.0f;
            gt[e] = gv; msum += gv;
        }
        float innorm = 1.0f / (msum + 1e-8f);
#pragma unroll
        for (int e = 0; e < 8; e++) mgs[tid * 8 + e] = gt[e] * innorm;
    }
    __syncthreads();            // router scratch in XF now dead

    // ---- pack x -> XF fp16 A-frags [t8][k8][l32] uint4 ----
#pragma unroll
    for (int it = 0; it < 8; it++) {
        int i = it * 256 + tid;            // = (t*8+k)*32 + l
        int l = i & 31, k = (i >> 5) & 7, t = i >> 8;
        int gg = l >> 2, cc = l & 3;
        const float* p0 = xp + (16 * t + gg) * XS + 16 * k + 2 * cc;
        uint4 v;
        v.x = h2u(__floats2half2_rn(p0[0], p0[1]));                       // row g,   k 2c..2c+1
        v.y = h2u(__floats2half2_rn(p0[8 * XS], p0[8 * XS + 1]));         // row g+8
        v.z = h2u(__floats2half2_rn(p0[8], p0[9]));                       // row g,   k 2c+8..2c+9
        v.w = h2u(__floats2half2_rn(p0[8 * XS + 8], p0[8 * XS + 9]));     // row g+8
        xfu[i] = v;
    }
    __syncthreads();            // XP now dead: ring buf2/buf3 may overlay it

    float facc[2][8][4];
#pragma unroll
    for (int i = 0; i < 2; i++)
#pragma unroll
        for (int j = 0; j < 8; j++)
#pragma unroll
            for (int r = 0; r < 4; r++) facc[i][j][r] = 0.0f;

    // ---- expert loop: 2 phases per expert, ONE sync per phase ----
    for (int e = 0; e < NEXP; e++) {
        float acc[2][8][4];
#pragma unroll
        for (int i = 0; i < 2; i++)
#pragma unroll
            for (int j = 0; j < 8; j++)
#pragma unroll
                for (int r = 0; r < 4; r++) acc[i][j][r] = 0.0f;

        // ===== phase s = 2e: GEMM1 from buf[(2e)&3] =====
        {
            int s = 2 * e;
            if (s + 2 < 20) issue(s + 2);
            CP_COMMIT();
            CP_WAIT2(); __syncthreads();   // chunk s ready; prior-phase reads all done
            const uint2* wr = (const uint2*)(smem + bufoff(s & 3));
#pragma unroll
            for (int k = 0; k < 8; k++) {
                unsigned a[2][4];
#pragma unroll
                for (int i = 0; i < 2; i++) {
                    uint4 av = xfu[((t0 + i) * 8 + k) * 32 + lane];
                    a[i][0] = av.x; a[i][1] = av.y; a[i][2] = av.z; a[i][3] = av.w;
                }
#pragma unroll
                for (int j = 0; j < 8; j++) {
                    uint2 bv = wr[(k * 16 + jb + j) * 32 + lane];
                    unsigned b[2] = { bv.x, bv.y };
                    mma_f16(acc[0][j], a[0], b);
                    mma_f16(acc[1][j], a[1], b);
                }
            }
        }

        // ===== epilogue: h = fp16(mg * gelu(acc + b1)) -> HF in A-frag layout =====
        {
            const float* b1 = b1s + e * 128;
#pragma unroll
            for (int i = 0; i < 2; i++) {
                int row0 = mrow + i * 16 + g;
                float w0 = (e < NRE) ? mgs[row0 * 8 + e] : 1.0f;
                float w1 = (e < NRE) ? mgs[(row0 + 8) * 8 + e] : 1.0f;
#pragma unroll
                for (int kp = 0; kp < 4; kp++) {
                    int jlo = 2 * kp, jhi = 2 * kp + 1;
                    int clo = 16 * (kb2 + kp) + 2 * c;
                    float blo0 = b1[clo], blo1 = b1[clo + 1];
                    float bhi0 = b1[clo + 8], bhi1 = b1[clo + 9];
                    uint4 v;
                    v.x = h2u(__floats2half2_rn(w0 * gelu_tanh(acc[i][jlo][0] + blo0),
                                                w0 * gelu_tanh(acc[i][jlo][1] + blo1)));
                    v.y = h2u(__floats2half2_rn(w1 * gelu_tanh(acc[i][jlo][2] + blo0),
                                                w1 * gelu_tanh(acc[i][jlo][3] + blo1)));
                    v.z = h2u(__floats2half2_rn(w0 * gelu_tanh(acc[i][jhi][0] + bhi0),
                                                w0 * gelu_tanh(acc[i][jhi][1] + bhi1)));
                    v.w = h2u(__floats2half2_rn(w1 * gelu_tanh(acc[i][jhi][2] + bhi0),
                                                w1 * gelu_tanh(acc[i][jhi][3] + bhi1)));
                    hfu[((t0 + i) * 8 + kb2 + kp) * 32 + lane] = v;
                }
            }
        }

        // ===== phase s = 2e+1: GEMM2 from buf[(2e+1)&3] (sync also publishes h) =====
        {
            int s = 2 * e + 1;
            if (s + 2 < 20) issue(s + 2);
            CP_COMMIT();
            CP_WAIT2(); __syncthreads();   // chunk s ready AND hfu published
            const uint2* wr = (const uint2*)(smem + bufoff(s & 3));
#pragma unroll
            for (int k = 0; k < 8; k++) {
                unsigned a[2][4];
#pragma unroll
                for (int i = 0; i < 2; i++) {
                    uint4 av = hfu[((t0 + i) * 8 + k) * 32 + lane];
                    a[i][0] = av.x; a[i][1] = av.y; a[i][2] = av.z; a[i][3] = av.w;
                }
#pragma unroll
                for (int j = 0; j < 8; j++) {
                    uint2 bv = wr[(k * 16 + jb + j) * 32 + lane];
                    unsigned b[2] = { bv.x, bv.y };
                    mma_f16(facc[0][j], a[0], b);
                    mma_f16(facc[1][j], a[1], b);
                }
            }
        }
    }

    // ---- writeout: facc + rank-10 bias correction ----
#pragma unroll
    for (int i = 0; i < 2; i++)
#pragma unroll
        for (int j = 0; j < 8; j++)
#pragma unroll
            for (int rr = 0; rr < 2; rr++) {
                int row = mrow + i * 16 + g + rr * 8;
                int col = jb * 8 + j * 8 + 2 * c;
                float v0 = facc[i][j][rr * 2 + 0];
                float v1 = facc[i][j][rr * 2 + 1];
#pragma unroll
                for (int e = 0; e < NRE; e++) {
                    float w = mgs[row * 8 + e];
                    v0 += w * b2s[e * 128 + col];
                    v1 += w * b2s[e * 128 + col + 1];
                }
                v0 += b2s[8 * 128 + col] + b2s[9 * 128 + col];
                v1 += b2s[8 * 128 + col + 1] + b2s[9 * 128 + col + 1];
                *reinterpret_cast<float2*>(out + (base + row) * 128 + col) = make_float2(v0, v1);
            }
}

extern "C" void kernel_launch(void* const* d_in, const int* in_sizes, int n_in,
                              void* d_out, int out_size) {
    const float* x   = (const float*)d_in[0];
    const float* Wr1 = (const float*)d_in[1];
    const float* br1 = (const float*)d_in[2];
    const float* Wr2 = (const float*)d_in[3];
    const float* br2 = (const float*)d_in[4];
    const float* We1 = (const float*)d_in[5];
    const float* be1 = (const float*)d_in[6];
    const float* We2 = (const float*)d_in[7];
    const float* be2 = (const float*)d_in[8];
    const float* Ws1 = (const float*)d_in[9];
    const float* bs1 = (const float*)d_in[10];
    const float* Ws2 = (const float*)d_in[11];
    const float* bs2 = (const float*)d_in[12];
    float* out = (float*)d_out;

    size_t prep_smem = 128 * XS * sizeof(float);
    cudaFuncSetAttribute(prep_kernel, cudaFuncAttributeMaxDynamicSharedMemorySize, (int)prep_smem);
    prep_kernel<<<20, 256, prep_smem>>>(We1, Ws1, We2, Ws2);

    int ntok = in_sizes[0] / 128;
    int grid = ntok / 128;
    cudaFuncSetAttribute(moe_kernel, cudaFuncAttributeMaxDynamicSharedMemorySize, SMEM_BYTES);
    moe_kernel<<<grid, 256, SMEM_BYTES>>>(x, Wr1, br1, Wr2, br2,
                                          be1, be2, bs1, bs2, out);
}

// round 17
// speedup vs baseline: 1.8640x; 1.0086x over previous
#include <cuda_runtime.h>
#include <cuda_fp16.h>
#include <cstdint>
#include <math.h>

#define NRE 8
#define NEXP 10
#define XS 132     // fp32 x staging row stride (floats)

// ---- dynamic smem byte offsets ----
// XP region [0, 67584) holds fp32 x staging during prologue; after the x-pack
// it is DEAD and weight ring buffers 2/3 overlay its first 65536 bytes.
#define XP_OFF   0          // 67584: fp32 x staging [128][132] / later ring buf2+buf3
#define XF_OFF   67584      // 32768: x A-frags fp16 [t8][k8][l32] uint4
#define HF_OFF   100352     // 32768: h A-frags fp16 [t8][k8][l32] uint4
#define WR_OFF   133120     // 65536: ring buf0 + buf1
#define MGS_OFF  198656     // 4096
#define B1S_OFF  202752     // 5120
#define B2S_OFF  207872     // 5120
#define SMEM_BYTES 212992

// fp16 paired-B-frag weight images: chunk s = 2e + {0:W1_e, 1:W2_e}, 32KB each.
// in-chunk: uint4 entry [(k8)*8 + jp][l32] packs B-frags of n8-tiles j=2jp and j=2jp+1:
//   .x/.y = b0/b1 of j=2jp   (n = 16jp + g)
//   .z/.w = b0/b1 of j=2jp+1 (n = 16jp + 8 + g)
__device__ __align__(16) uint4 g_wfrag[20 * 2048];

// ---------------- helpers ----------------
static __device__ __forceinline__ uint32_t s2u(const void* p) {
    uint32_t a;
    asm("{ .reg .u64 t; cvta.to.shared.u64 t, %1; cvt.u32.u64 %0, t; }" : "=r"(a) : "l"(p));
    return a;
}
static __device__ __forceinline__ unsigned h2u(__half2 h) {
    return *reinterpret_cast<unsigned*>(&h);
}
static __device__ __forceinline__ void mma_f16(float d[4], const unsigned a[4], const unsigned b[2]) {
    asm volatile(
        "mma.sync.aligned.m16n8k16.row.col.f32.f16.f16.f32 "
        "{%0,%1,%2,%3}, {%4,%5,%6,%7}, {%8,%9}, {%0,%1,%2,%3};"
        : "+f"(d[0]), "+f"(d[1]), "+f"(d[2]), "+f"(d[3])
        : "r"(a[0]), "r"(a[1]), "r"(a[2]), "r"(a[3]), "r"(b[0]), "r"(b[1]));
}
// gelu with single-MUFU hardware tanh (sm_75+)
static __device__ __forceinline__ float gelu_tanh(float x) {
    float u = 0.7978845608028654f * (x + 0.044715f * x * x * x);
    float t;
    asm("tanh.approx.f32 %0, %1;" : "=f"(t) : "f"(u));
    return 0.5f * x * (1.0f + t);
}
static __device__ __forceinline__ void cp16(uint32_t dst, const void* src) {
    asm volatile("cp.async.cg.shared.global [%0], [%1], 16;" :: "r"(dst), "l"(src) : "memory");
}
#define CP_COMMIT() asm volatile("cp.async.commit_group;" ::: "memory")
#define CP_WAIT2()  asm volatile("cp.async.wait_group 2;" ::: "memory")

// ============ prep: weights -> fp16 paired-B-frag chunks (one matrix per block) ============
__global__ void __launch_bounds__(256, 1)
prep_kernel(const float* __restrict__ We1, const float* __restrict__ Ws1,
            const float* __restrict__ We2, const float* __restrict__ Ws2) {
    extern __shared__ float ws[];          // [128][132]
    int m = blockIdx.x;                    // 0..7 We1, 8..9 Ws1, 10..17 We2, 18..19 Ws2
    const float* W;
    int ee, isw2;
    if (m < 8)       { W = We1 + m * 16384;        ee = m;      isw2 = 0; }
    else if (m < 10) { W = Ws1 + (m - 8) * 16384;  ee = m;      isw2 = 0; }
    else if (m < 18) { W = We2 + (m - 10) * 16384; ee = m - 10; isw2 = 1; }
    else             { W = Ws2 + (m - 18) * 16384; ee = m - 10; isw2 = 1; }
    const int tid = threadIdx.x;
#pragma unroll
    for (int it = 0; it < 16; it++) {
        int idx = it * 256 + tid;
        int row = idx >> 5, c4 = (idx & 31) << 2;
        *reinterpret_cast<float4*>(ws + row * XS + c4) =
            *reinterpret_cast<const float4*>(W + row * 128 + c4);
    }
    __syncthreads();
    uint4* dst = g_wfrag + (size_t)(2 * ee + isw2) * 2048;
#pragma unroll
    for (int it = 0; it < 8; it++) {
        int i = it * 256 + tid;            // 0..2047: [k8][jp8][l32]
        int l = i & 31, jp = (i >> 5) & 7, k = i >> 8;
        int g = l >> 2, c = l & 3;
        int nlo = 16 * jp + g;
        int nhi = nlo + 8;
        int r = 16 * k + 2 * c;
        uint4 o;
        o.x = h2u(__floats2half2_rn(ws[r * XS + nlo],       ws[(r + 1) * XS + nlo]));
        o.y = h2u(__floats2half2_rn(ws[(r + 8) * XS + nlo], ws[(r + 9) * XS + nlo]));
        o.z = h2u(__floats2half2_rn(ws[r * XS + nhi],       ws[(r + 1) * XS + nhi]));
        o.w = h2u(__floats2half2_rn(ws[(r + 8) * XS + nhi], ws[(r + 9) * XS + nhi]));
        dst[i] = o;
    }
}

// ============ main fused kernel: register-resident x A-frags + paired-B ============
__global__ void __launch_bounds__(256, 1)
moe_kernel(const float* __restrict__ x,
           const float* __restrict__ Wr1, const float* __restrict__ br1,
           const float* __restrict__ Wr2, const float* __restrict__ br2,
           const float* __restrict__ be1, const float* __restrict__ be2,
           const float* __restrict__ bs1, const float* __restrict__ bs2,
           float* __restrict__ out) {
    extern __shared__ char smem[];
    const uint32_t sb = s2u(smem);
    float* xp  = (float*)(smem + XP_OFF);
    uint4* xfu = (uint4*)(smem + XF_OFF);
    uint4* hfu = (uint4*)(smem + HF_OFF);
    float* mgs = (float*)(smem + MGS_OFF);
    float* b1s = (float*)(smem + B1S_OFF);
    float* b2s = (float*)(smem + B2S_OFF);
    // router scratch overlays XF (packed only after router completes)
    float* rW1 = (float*)(smem + XF_OFF);
    float* rb1 = rW1 + 2048;
    float* rW2 = rW1 + 2064;
    float* rb2 = rW1 + 2192;
    float* rfb = rW1 + 2208;

    const int tid  = threadIdx.x;
    const int lane = tid & 31;
    const int wid  = tid >> 5;
    const int g    = lane >> 2;
    const int c    = lane & 3;
    const int t0   = (wid >> 1) * 2;       // first 16-row tile of this warp
    const int mrow = t0 * 16;
    const int jpb  = (wid & 1) * 4;        // first jp (4 pairs = 8 n8-tiles = 64 cols)
    const int jb   = (wid & 1) * 8;        // first n8 tile (epilogue/writeout indexing)
    const int kb2  = (wid & 1) * 4;        // warp's k'-slice base for h A-frags
    const long base = (long)blockIdx.x * 128;

    // ring buffer idx -> smem byte offset (buf0/1 in WR region, buf2/3 overlay XP)
    auto bufoff = [&](int idx) -> uint32_t {
        return (idx < 2) ? (uint32_t)WR_OFF + (uint32_t)idx * 32768u
                         : (uint32_t)(idx - 2) * 32768u;
    };
    auto issue = [&](int s) {
        uint32_t d = sb + bufoff(s & 3);
        const char* src = (const char*)g_wfrag + (size_t)s * 32768;
#pragma unroll
        for (int i = 0; i < 8; i++) {
            uint32_t o = (uint32_t)(tid + i * 256) * 16u;
            cp16(d + o, src + o);
        }
    };

    // ---- prologue: chunks 0,1 -> buf0,buf1 (WR region; safe before staging) ----
    issue(0); CP_COMMIT();
    issue(1); CP_COMMIT();

    // ---- stage x (fp32) + biases + router weights ----
#pragma unroll
    for (int it = 0; it < 16; it++) {
        int idx = it * 256 + tid;
        int row = idx >> 5, c4 = (idx & 31) << 2;
        float4 v = *reinterpret_cast<const float4*>(x + (base + row) * 128 + c4);
        *reinterpret_cast<float4*>(xp + row * XS + c4) = v;
    }
    for (int i = tid; i < 1280; i += 256) b1s[i] = (i < 1024) ? be1[i] : bs1[i - 1024];
    for (int i = tid; i < 1280; i += 256) b2s[i] = (i < 1024) ? be2[i] : bs2[i - 1024];
    for (int i = tid; i < 2048; i += 256) rW1[i] = Wr1[i];
    if (tid < 16)  rb1[tid] = br1[tid];
    if (tid < 128) rW2[tid] = Wr2[tid];
    if (tid < 8)   rb2[tid] = br2[tid];
    __syncthreads();

    // ---- router stage 1 (fp32, full precision) ----
    {
        int tok = tid & 127, jfb = (tid >> 7) * 8;
        float rf[8];
#pragma unroll
        for (int j = 0; j < 8; j++) rf[j] = rb1[jfb + j];
        for (int h = 0; h < 128; h++) {
            float xv = xp[tok * XS + h];
#pragma unroll
            for (int j = 0; j < 8; j++) rf[j] += xv * rW1[h * 16 + jfb + j];
        }
#pragma unroll
        for (int j = 0; j < 8; j++) rfb[tok * 16 + jfb + j] = fmaxf(rf[j], 0.0f);
    }
    __syncthreads();
    // ---- router stage 2: softmax -> threshold -> renorm ----
    if (tid < 128) {
        float lg[8];
#pragma unroll
        for (int e = 0; e < 8; e++) lg[e] = rb2[e];
#pragma unroll
        for (int r = 0; r < 16; r++) {
            float v = rfb[tid * 16 + r];
#pragma unroll
            for (int e = 0; e < 8; e++) lg[e] += v * rW2[r * 8 + e];
        }
        float mx = lg[0];
#pragma unroll
        for (int e = 1; e < 8; e++) mx = fmaxf(mx, lg[e]);
        float s = 0.0f, gt[8];
#pragma unroll
        for (int e = 0; e < 8; e++) { gt[e] = expf(lg[e] - mx); s += gt[e]; }
        float inv = 1.0f / s, msum = 0.0f;
#pragma unroll
        for (int e = 0; e < 8; e++) {
            float gv = gt[e] * inv;
            gv = (gv > 0.125f) ? gv : 0.0f;
            gt[e] = gv; msum += gv;
        }
        float innorm = 1.0f / (msum + 1e-8f);
#pragma unroll
        for (int e = 0; e < 8; e++) mgs[tid * 8 + e] = gt[e] * innorm;
    }
    __syncthreads();            // router scratch in XF now dead

    // ---- pack x -> XF fp16 A-frags [t8][k8][l32] uint4 ----
#pragma unroll
    for (int it = 0; it < 8; it++) {
        int i = it * 256 + tid;            // = (t*8+k)*32 + l
        int l = i & 31, k = (i >> 5) & 7, t = i >> 8;
        int gg = l >> 2, cc = l & 3;
        const float* p0 = xp + (16 * t + gg) * XS + 16 * k + 2 * cc;
        uint4 v;
        v.x = h2u(__floats2half2_rn(p0[0], p0[1]));                       // row g,   k 2c..2c+1
        v.y = h2u(__floats2half2_rn(p0[8 * XS], p0[8 * XS + 1]));         // row g+8
        v.z = h2u(__floats2half2_rn(p0[8], p0[9]));                       // row g,   k 2c+8..2c+9
        v.w = h2u(__floats2half2_rn(p0[8 * XS + 8], p0[8 * XS + 9]));     // row g+8
        xfu[i] = v;
    }
    __syncthreads();            // XP now dead: ring buf2/buf3 may overlay it

    // ---- hoist x A-frags into registers (invariant across all 10 GEMM1s) ----
    uint4 xfr[2][8];
#pragma unroll
    for (int i = 0; i < 2; i++)
#pragma unroll
        for (int k = 0; k < 8; k++)
            xfr[i][k] = xfu[((t0 + i) * 8 + k) * 32 + lane];

    float facc[2][8][4];
#pragma unroll
    for (int i = 0; i < 2; i++)
#pragma unroll
        for (int j = 0; j < 8; j++)
#pragma unroll
            for (int r = 0; r < 4; r++) facc[i][j][r] = 0.0f;

    // ---- expert loop: 2 phases per expert, ONE sync per phase ----
    for (int e = 0; e < NEXP; e++) {
        float acc[2][8][4];
#pragma unroll
        for (int i = 0; i < 2; i++)
#pragma unroll
            for (int j = 0; j < 8; j++)
#pragma unroll
                for (int r = 0; r < 4; r++) acc[i][j][r] = 0.0f;

        // ===== phase s = 2e: GEMM1, A from registers, paired-B from buf[(2e)&3] =====
        {
            int s = 2 * e;
            if (s + 2 < 20) issue(s + 2);
            CP_COMMIT();
            CP_WAIT2(); __syncthreads();   // chunk s ready; prior-phase reads all done
            const uint4* wr = (const uint4*)(smem + bufoff(s & 3));
#pragma unroll
            for (int k = 0; k < 8; k++) {
                unsigned a0[4] = { xfr[0][k].x, xfr[0][k].y, xfr[0][k].z, xfr[0][k].w };
                unsigned a1[4] = { xfr[1][k].x, xfr[1][k].y, xfr[1][k].z, xfr[1][k].w };
#pragma unroll
                for (int jp = 0; jp < 4; jp++) {
                    uint4 bv = wr[(k * 8 + jpb + jp) * 32 + lane];
                    unsigned b0[2] = { bv.x, bv.y };
                    unsigned b1[2] = { bv.z, bv.w };
                    mma_f16(acc[0][2 * jp],     a0, b0);
                    mma_f16(acc[1][2 * jp],     a1, b0);
                    mma_f16(acc[0][2 * jp + 1], a0, b1);
                    mma_f16(acc[1][2 * jp + 1], a1, b1);
                }
            }
        }

        // ===== epilogue: h = fp16(mg * gelu(acc + b1)) -> HF in A-frag layout =====
        {
            const float* b1 = b1s + e * 128;
#pragma unroll
            for (int i = 0; i < 2; i++) {
                int row0 = mrow + i * 16 + g;
                float w0 = (e < NRE) ? mgs[row0 * 8 + e] : 1.0f;
                float w1 = (e < NRE) ? mgs[(row0 + 8) * 8 + e] : 1.0f;
#pragma unroll
                for (int kp = 0; kp < 4; kp++) {
                    int jlo = 2 * kp, jhi = 2 * kp + 1;
                    int clo = 16 * (kb2 + kp) + 2 * c;
                    float blo0 = b1[clo], blo1 = b1[clo + 1];
                    float bhi0 = b1[clo + 8], bhi1 = b1[clo + 9];
                    uint4 v;
                    v.x = h2u(__floats2half2_rn(w0 * gelu_tanh(acc[i][jlo][0] + blo0),
                                                w0 * gelu_tanh(acc[i][jlo][1] + blo1)));
                    v.y = h2u(__floats2half2_rn(w1 * gelu_tanh(acc[i][jlo][2] + blo0),
                                                w1 * gelu_tanh(acc[i][jlo][3] + blo1)));
                    v.z = h2u(__floats2half2_rn(w0 * gelu_tanh(acc[i][jhi][0] + bhi0),
                                                w0 * gelu_tanh(acc[i][jhi][1] + bhi1)));
                    v.w = h2u(__floats2half2_rn(w1 * gelu_tanh(acc[i][jhi][2] + bhi0),
                                                w1 * gelu_tanh(acc[i][jhi][3] + bhi1)));
                    hfu[((t0 + i) * 8 + kb2 + kp) * 32 + lane] = v;
                }
            }
        }

        // ===== phase s = 2e+1: GEMM2, A = HF, paired-B from buf[(2e+1)&3] =====
        {
            int s = 2 * e + 1;
            if (s + 2 < 20) issue(s + 2);
            CP_COMMIT();
            CP_WAIT2(); __syncthreads();   // chunk s ready AND hfu published
            const uint4* wr = (const uint4*)(smem + bufoff(s & 3));
#pragma unroll
            for (int k = 0; k < 8; k++) {
                uint4 av0 = hfu[((t0 + 0) * 8 + k) * 32 + lane];
                uint4 av1 = hfu[((t0 + 1) * 8 + k) * 32 + lane];
                unsigned a0[4] = { av0.x, av0.y, av0.z, av0.w };
                unsigned a1[4] = { av1.x, av1.y, av1.z, av1.w };
#pragma unroll
                for (int jp = 0; jp < 4; jp++) {
                    uint4 bv = wr[(k * 8 + jpb + jp) * 32 + lane];
                    unsigned b0[2] = { bv.x, bv.y };
                    unsigned b1[2] = { bv.z, bv.w };
                    mma_f16(facc[0][2 * jp],     a0, b0);
                    mma_f16(facc[1][2 * jp],     a1, b0);
                    mma_f16(facc[0][2 * jp + 1], a0, b1);
                    mma_f16(facc[1][2 * jp + 1], a1, b1);
                }
            }
        }
    }

    // ---- writeout: facc + rank-10 bias correction ----
#pragma unroll
    for (int i = 0; i < 2; i++)
#pragma unroll
        for (int j = 0; j < 8; j++)
#pragma unroll
            for (int rr = 0; rr < 2; rr++) {
                int row = mrow + i * 16 + g + rr * 8;
                int col = jb * 8 + j * 8 + 2 * c;
                float v0 = facc[i][j][rr * 2 + 0];
                float v1 = facc[i][j][rr * 2 + 1];
#pragma unroll
                for (int e = 0; e < NRE; e++) {
                    float w = mgs[row * 8 + e];
                    v0 += w * b2s[e * 128 + col];
                    v1 += w * b2s[e * 128 + col + 1];
                }
                v0 += b2s[8 * 128 + col] + b2s[9 * 128 + col];
                v1 += b2s[8 * 128 + col + 1] + b2s[9 * 128 + col + 1];
                *reinterpret_cast<float2*>(out + (base + row) * 128 + col) = make_float2(v0, v1);
            }
}

extern "C" void kernel_launch(void* const* d_in, const int* in_sizes, int n_in,
                              void* d_out, int out_size) {
    const float* x   = (const float*)d_in[0];
    const float* Wr1 = (const float*)d_in[1];
    const float* br1 = (const float*)d_in[2];
    const float* Wr2 = (const float*)d_in[3];
    const float* br2 = (const float*)d_in[4];
    const float* We1 = (const float*)d_in[5];
    const float* be1 = (const float*)d_in[6];
    const float* We2 = (const float*)d_in[7];
    const float* be2 = (const float*)d_in[8];
    const float* Ws1 = (const float*)d_in[9];
    const float* bs1 = (const float*)d_in[10];
    const float* Ws2 = (const float*)d_in[11];
    const float* bs2 = (const float*)d_in[12];
    float* out = (float*)d_out;

    size_t prep_smem = 128 * XS * sizeof(float);
    cudaFuncSetAttribute(prep_kernel, cudaFuncAttributeMaxDynamicSharedMemorySize, (int)prep_smem);
    prep_kernel<<<20, 256, prep_smem>>>(We1, Ws1, We2, Ws2);

    int ntok = in_sizes[0] / 128;
    int grid = ntok / 128;
    cudaFuncSetAttribute(moe_kernel, cudaFuncAttributeMaxDynamicSharedMemorySize, SMEM_BYTES);
    moe_kernel<<<grid, 256, SMEM_BYTES>>>(x, Wr1, br1, Wr2, br2,
                                          be1, be2, bs1, bs2, out);
}